// round 17
// baseline (speedup 1.0000x reference)
#include <cuda_runtime.h>

#define MM 361
#define LL 359
#define MPAD 384

#define X_ELEMS  33177600   // 8*8*2*360*720
#define W_ELEMS  93311280   // 2*361*359*360

// ---------------- packed f32x2 helpers (sm_103a FFMA2) --------------------------
__device__ __forceinline__ void fma_x2(unsigned long long& d,
                                       unsigned long long a,
                                       unsigned long long b) {
    asm("fma.rn.f32x2 %0, %1, %2, %0;" : "+l"(d) : "l"(a), "l"(b));
}
__device__ __forceinline__ unsigned long long pk2(float lo, float hi) {
    unsigned long long r;
    asm("mov.b64 %0, {%1, %2};" : "=l"(r) : "f"(lo), "f"(hi));
    return r;
}
__device__ __forceinline__ float2 upk2(unsigned long long v) {
    float2 r;
    asm("mov.b64 {%0, %1}, %2;" : "=f"(r.x), "=f"(r.y) : "l"(v));
    return r;
}

// ---------------- device scratch -------------------------------------------------
__device__ float g_ct[361 * MPAD];           // s*cos(2pi m n/720), row n
__device__ float g_st[359 * MPAD];           // -s*sin(2pi m n/720), row n-1
__device__ float g_xf[361u * 360u * 256u];   // [m][k][comp*64+b] 0=ar 1=ai 2=br 3=bi

// ---------------- twiddle tables (MUFU only) -------------------------------------
__global__ void __launch_bounds__(256) k_tables() {
    int id = blockIdx.x * blockDim.x + threadIdx.x;
    const float s  = 8.7266462599716478846e-3f;   // 2*pi/720
    const float a0 = 8.7266462599716478846e-3f;   // pi/360
    if (id < 361 * MPAD) {
        int n = id / MPAD, m = id % MPAD;
        float v = 0.f;
        if (m < 361) {
            int p = (m * n) % 720;
            float sn, cs; __sincosf(a0 * (float)p, &sn, &cs);
            v = s * cs;
        }
        g_ct[id] = v;
    } else {
        int id2 = id - 361 * MPAD;
        if (id2 < 359 * MPAD) {
            int n = id2 / MPAD + 1, m = id2 % MPAD;
            float v = 0.f;
            if (m < 361) {
                int p = (m * n) % 720;
                float sn, cs; __sincosf(a0 * (float)p, &sn, &cs);
                v = -s * sn;
            }
            g_st[id2] = v;
        }
    }
}

// ---------------- stage 1: folded DFT as GEMM (packed FFMA2) ---------------------
// grid (6 m-tiles of 64, 720 (k,c)). block 256 = 16 m-grp x 16 b-grp, 4m x 4b tile.
__global__ void __launch_bounds__(256) k_dft(const float* __restrict__ x) {
    const int mt = blockIdx.x;
    const int ck = blockIdx.y;
    const int c = ck & 1, k = ck >> 1;
    const int tid = threadIdx.x;
    const int tm = tid >> 4, tb = tid & 15;
    const int m_off = tm * 4, b_off = tb * 4;
    const int m0 = mt * 64;
    const int lane = tid & 31;
    const int wrp  = tid >> 5;

    __shared__ float es[32][68];   // [n][b]; stride 68 floats = 272B (16B mult)
    __shared__ float ts[32][64];   // [n][m]

    unsigned long long aR2[4][2], aI2[4][2];
#pragma unroll
    for (int i = 0; i < 4; i++) {
        aR2[i][0] = 0ULL; aR2[i][1] = 0ULL;
        aI2[i][0] = 0ULL; aI2[i][1] = 0ULL;
    }

    // ---- cos/even pass: n = 0..360 ----
    for (int n0 = 0; n0 < 361; n0 += 32) {
#pragma unroll
        for (int j = 0; j < 8; j++) {
            int cb = wrp + j * 8;
            int n  = n0 + lane;
            const float* row = x + ((size_t)((cb * 2 + c) * 360 + k)) * 720;
            float v = 0.f;
            if (n < 361) {
                float xn = row[n];
                float xr = (n >= 1 && n <= 359) ? row[720 - n] : 0.f;
                v = xn + xr;
            }
            es[lane][cb] = v;
        }
#pragma unroll
        for (int j = 0; j < 8; j++) {
            int i = tid + j * 256;
            int nn = i >> 6, cb = i & 63;
            int n  = n0 + nn;
            ts[nn][cb] = (n < 361) ? g_ct[n * MPAD + m0 + cb] : 0.f;
        }
        __syncthreads();
#pragma unroll
        for (int nn = 0; nn < 32; nn++) {
            unsigned long long e01 = *(const unsigned long long*)&es[nn][b_off];
            unsigned long long e23 = *(const unsigned long long*)&es[nn][b_off + 2];
            float4 tv = *(const float4*)&ts[nn][m_off];
            unsigned long long t0p = pk2(tv.x, tv.x);
            unsigned long long t1p = pk2(tv.y, tv.y);
            unsigned long long t2p = pk2(tv.z, tv.z);
            unsigned long long t3p = pk2(tv.w, tv.w);
            fma_x2(aR2[0][0], t0p, e01); fma_x2(aR2[0][1], t0p, e23);
            fma_x2(aR2[1][0], t1p, e01); fma_x2(aR2[1][1], t1p, e23);
            fma_x2(aR2[2][0], t2p, e01); fma_x2(aR2[2][1], t2p, e23);
            fma_x2(aR2[3][0], t3p, e01); fma_x2(aR2[3][1], t3p, e23);
        }
        __syncthreads();
    }

    // ---- sin/odd pass: n = np+1, np = 0..358 ----
    for (int n0 = 0; n0 < 359; n0 += 32) {
#pragma unroll
        for (int j = 0; j < 8; j++) {
            int cb = wrp + j * 8;
            int np = n0 + lane;
            const float* row = x + ((size_t)((cb * 2 + c) * 360 + k)) * 720;
            float v = 0.f;
            if (np < 359) v = row[np + 1] - row[719 - np];
            es[lane][cb] = v;
        }
#pragma unroll
        for (int j = 0; j < 8; j++) {
            int i = tid + j * 256;
            int nn = i >> 6, cb = i & 63;
            int np = n0 + nn;
            ts[nn][cb] = (np < 359) ? g_st[np * MPAD + m0 + cb] : 0.f;
        }
        __syncthreads();
#pragma unroll
        for (int nn = 0; nn < 32; nn++) {
            unsigned long long e01 = *(const unsigned long long*)&es[nn][b_off];
            unsigned long long e23 = *(const unsigned long long*)&es[nn][b_off + 2];
            float4 tv = *(const float4*)&ts[nn][m_off];
            unsigned long long t0p = pk2(tv.x, tv.x);
            unsigned long long t1p = pk2(tv.y, tv.y);
            unsigned long long t2p = pk2(tv.z, tv.z);
            unsigned long long t3p = pk2(tv.w, tv.w);
            fma_x2(aI2[0][0], t0p, e01); fma_x2(aI2[0][1], t0p, e23);
            fma_x2(aI2[1][0], t1p, e01); fma_x2(aI2[1][1], t1p, e23);
            fma_x2(aI2[2][0], t2p, e01); fma_x2(aI2[2][1], t2p, e23);
            fma_x2(aI2[3][0], t3p, e01); fma_x2(aI2[3][1], t3p, e23);
        }
        __syncthreads();
    }

    const int cr = 2 * c, ci = 2 * c + 1;
#pragma unroll
    for (int i = 0; i < 4; i++) {
        int m = m0 + m_off + i;
        if (m < 361) {
            float* dst = g_xf + ((size_t)m * 360 + k) * 256;
            float2 r0 = upk2(aR2[i][0]), r1 = upk2(aR2[i][1]);
            float2 q0 = upk2(aI2[i][0]), q1 = upk2(aI2[i][1]);
            dst[cr * 64 + b_off + 0] = r0.x;
            dst[cr * 64 + b_off + 1] = r0.y;
            dst[cr * 64 + b_off + 2] = r1.x;
            dst[cr * 64 + b_off + 3] = r1.y;
            dst[ci * 64 + b_off + 0] = q0.x;
            dst[ci * 64 + b_off + 1] = q0.y;
            dst[ci * 64 + b_off + 2] = q1.x;
            dst[ci * 64 + b_off + 3] = q1.y;
        }
    }
}

// ---------------- stage 2: per-m GEMM over k (packed FFMA2), real-only ----------
// grid (361 m, 6 l-tiles of 64). block 256 = 16 tl x 16 tb. 4l x 4b thread tile.
__global__ void __launch_bounds__(256) k_sht(const float* __restrict__ w,
                                             float* __restrict__ out,
                                             long long out_cap) {
    const int m  = blockIdx.x;
    const int l0 = blockIdx.y * 64;
    const int tid = threadIdx.x;
    const int tl = tid >> 4, tb = tid & 15;

    __shared__ float As[2][24][68];   // [d][k][l], padded (stride 272B)
    __shared__ float Bs[24][256];     // [k][comp*64+b]

    unsigned long long q0ar[4][2], q0br[4][2], q1ai[4][2], q1bi[4][2];
#pragma unroll
    for (int i = 0; i < 4; i++) {
        q0ar[i][0] = 0ULL; q0ar[i][1] = 0ULL;
        q0br[i][0] = 0ULL; q0br[i][1] = 0ULL;
        q1ai[i][0] = 0ULL; q1ai[i][1] = 0ULL;
        q1bi[i][0] = 0ULL; q1bi[i][1] = 0ULL;
    }

    const size_t wpl = (size_t)LL * 360;               // 129240
    const float* w0 = w + (size_t)m * wpl;
    const float* w1 = w + (size_t)(MM + m) * wpl;
    const float* Bg = g_xf + (size_t)m * 360 * 256;

    for (int k0 = 0; k0 < 360; k0 += 24) {
        // As: 2*24*64 floats = 768 float4, 3 per thread, transpose to [k][l].
#pragma unroll
        for (int q = 0; q < 3; q++) {
            int idx = tid + q * 256;        // 0..767
            int d   = idx / 384;
            int r   = idx - d * 384;        // 0..383
            int li  = r / 6;                // 0..63
            int kq  = r - li * 6;           // 0..5
            int l   = l0 + li;
            float4 v = make_float4(0.f, 0.f, 0.f, 0.f);
            if (l < LL) {
                const float* src = (d ? w1 : w0) + (size_t)l * 360 + k0 + kq * 4;
                v = *(const float4*)src;
            }
            As[d][kq * 4 + 0][li] = v.x;
            As[d][kq * 4 + 1][li] = v.y;
            As[d][kq * 4 + 2][li] = v.z;
            As[d][kq * 4 + 3][li] = v.w;
        }
        // Bs: 24*256 floats = 1536 float4, 6 per thread, coalesced.
#pragma unroll
        for (int q = 0; q < 6; q++) {
            int fidx = tid + q * 256;
            int kk   = fidx >> 6;
            int c4   = fidx & 63;
            float4 v = *(const float4*)&Bg[(size_t)(k0 + kk) * 256 + c4 * 4];
            *(float4*)&Bs[kk][c4 * 4] = v;
        }
        __syncthreads();

#pragma unroll
        for (int kk = 0; kk < 24; kk++) {
            float4 a0 = *(const float4*)&As[0][kk][tl * 4];
            float4 a1 = *(const float4*)&As[1][kk][tl * 4];
            // b pairs straight from smem as u64 (offsets 16B/8B aligned)
            unsigned long long ar01 = *(const unsigned long long*)&Bs[kk][tb * 4];
            unsigned long long ar23 = *(const unsigned long long*)&Bs[kk][tb * 4 + 2];
            unsigned long long ai01 = *(const unsigned long long*)&Bs[kk][64 + tb * 4];
            unsigned long long ai23 = *(const unsigned long long*)&Bs[kk][64 + tb * 4 + 2];
            unsigned long long br01 = *(const unsigned long long*)&Bs[kk][128 + tb * 4];
            unsigned long long br23 = *(const unsigned long long*)&Bs[kk][128 + tb * 4 + 2];
            unsigned long long bi01 = *(const unsigned long long*)&Bs[kk][192 + tb * 4];
            unsigned long long bi23 = *(const unsigned long long*)&Bs[kk][192 + tb * 4 + 2];

            unsigned long long a0p[4], a1p[4];
            a0p[0] = pk2(a0.x, a0.x); a0p[1] = pk2(a0.y, a0.y);
            a0p[2] = pk2(a0.z, a0.z); a0p[3] = pk2(a0.w, a0.w);
            a1p[0] = pk2(a1.x, a1.x); a1p[1] = pk2(a1.y, a1.y);
            a1p[2] = pk2(a1.z, a1.z); a1p[3] = pk2(a1.w, a1.w);
#pragma unroll
            for (int i = 0; i < 4; i++) {
                fma_x2(q0ar[i][0], a0p[i], ar01); fma_x2(q0ar[i][1], a0p[i], ar23);
                fma_x2(q0br[i][0], a0p[i], br01); fma_x2(q0br[i][1], a0p[i], br23);
                fma_x2(q1ai[i][0], a1p[i], ai01); fma_x2(q1ai[i][1], a1p[i], ai23);
                fma_x2(q1bi[i][0], a1p[i], bi01); fma_x2(q1bi[i][1], a1p[i], bi23);
            }
        }
        __syncthreads();
    }

    // combine + store real parts: out[((b*2+ch)*359 + l)*361 + m]
#pragma unroll
    for (int i = 0; i < 4; i++) {
        int l = l0 + tl * 4 + i;
        if (l < LL) {
            float2 v0ar0 = upk2(q0ar[i][0]), v0ar1 = upk2(q0ar[i][1]);
            float2 v0br0 = upk2(q0br[i][0]), v0br1 = upk2(q0br[i][1]);
            float2 v1ai0 = upk2(q1ai[i][0]), v1ai1 = upk2(q1ai[i][1]);
            float2 v1bi0 = upk2(q1bi[i][0]), v1bi1 = upk2(q1bi[i][1]);
            float p0ar[4] = {v0ar0.x, v0ar0.y, v0ar1.x, v0ar1.y};
            float p0br[4] = {v0br0.x, v0br0.y, v0br1.x, v0br1.y};
            float p1ai[4] = {v1ai0.x, v1ai0.y, v1ai1.x, v1ai1.y};
            float p1bi[4] = {v1bi0.x, v1bi0.y, v1bi1.x, v1bi1.y};
#pragma unroll
            for (int j = 0; j < 4; j++) {
                int b = tb * 4 + j;
                float o0r =  p0ar[j] - p1bi[j];
                float o1r = -p1ai[j] - p0br[j];
                long long i0 = ((long long)(b * 2 + 0) * LL + l) * MM + m;
                long long i1 = ((long long)(b * 2 + 1) * LL + l) * MM + m;
                if (i0 < out_cap) out[i0] = o0r;
                if (i1 < out_cap) out[i1] = o1r;
            }
        }
    }
}

// ---------------- launch ----------------------------------------------------------
extern "C" void kernel_launch(void* const* d_in, const int* in_sizes, int n_in,
                              void* d_out, int out_size) {
    if (n_in < 2 || d_in == nullptr || d_out == nullptr) return;

    int xi = -1, wi = -1;
    for (int i = 0; i < n_in; i++) {
        if (in_sizes[i] == X_ELEMS && xi < 0) xi = i;
        if (in_sizes[i] == W_ELEMS && wi < 0) wi = i;
    }
    if (xi < 0 || wi < 0 || xi == wi) return;

    const float* x = (const float*)d_in[xi];
    const float* w = (const float*)d_in[wi];
    if (x == nullptr || w == nullptr) return;

    long long out_cap = (long long)out_size;
    if (out_cap < 0) out_cap = 0;

    {
        int total = 361 * MPAD + 359 * MPAD;
        k_tables<<<(total + 255) / 256, 256>>>();
    }
    {
        dim3 g(6, 720);
        k_dft<<<g, 256>>>(x);
    }
    {
        dim3 g(361, 6);
        k_sht<<<g, 256>>>(w, (float*)d_out, out_cap);
    }
}